// round 2
// baseline (speedup 1.0000x reference)
#include <cuda_runtime.h>
#include <cuda_bf16.h>

// OHEM loss, C=1 specialization:
//   ce == 0 exactly (logsumexp over singleton axis minus the gathered element),
//   so cls_loss == 0 and the hard-negative mining is dead code.
//   out = 0.2 * sum_{pos}(smoothL1(loc_preds - loc_targets)) / num_pos
//
// Single fused kernel: grid-wide masked reduction, last-arriving block folds
// the per-block partials and writes the scalar (threadfence + ticket pattern).

#define NBLOCKS  1184   // 148 SMs * 8 blocks
#define NTHREADS 256
#define NWARPS   (NTHREADS / 32)

__device__ float g_partial_sum[NBLOCKS];
__device__ int   g_partial_cnt[NBLOCKS];
__device__ int   g_ticket = 0;          // self-resetting; deterministic output

__device__ __forceinline__ float smooth_l1(float d) {
    float ax = fabsf(d);
    return (ax < 1.0f) ? 0.5f * d * d : ax - 0.5f;
}

__device__ __forceinline__ float anchor_loss(const float4* __restrict__ lp,
                                             const float4* __restrict__ lt,
                                             int i) {
    float4 p0 = lp[2 * i];
    float4 p1 = lp[2 * i + 1];
    float4 t0 = lt[2 * i];
    float4 t1 = lt[2 * i + 1];
    float s = smooth_l1(p0.x - t0.x);
    s += smooth_l1(p0.y - t0.y);
    s += smooth_l1(p0.z - t0.z);
    s += smooth_l1(p0.w - t0.w);
    s += smooth_l1(p1.x - t1.x);
    s += smooth_l1(p1.y - t1.y);
    s += smooth_l1(p1.z - t1.z);
    s += smooth_l1(p1.w - t1.w);
    return s;
}

__global__ __launch_bounds__(NTHREADS, 8)
void ohem_fused_kernel(const float4* __restrict__ lp,   // loc_preds  (2 float4 / anchor)
                       const float4* __restrict__ lt,   // loc_targets
                       const int4*   __restrict__ ct4,  // cls_targets as int4
                       int nGroups,                     // nAnchors / 4 (exact)
                       float* __restrict__ out)
{
    float sum = 0.0f;
    int   cnt = 0;

    const int stride = gridDim.x * blockDim.x;
    for (int g = blockIdx.x * blockDim.x + threadIdx.x; g < nGroups; g += stride) {
        int4 t = ct4[g];
        int base = 4 * g;
        // Independent predicated loads for 4 anchors -> deep MLP.
        if (t.x > 0) { sum += anchor_loss(lp, lt, base + 0); cnt++; }
        if (t.y > 0) { sum += anchor_loss(lp, lt, base + 1); cnt++; }
        if (t.z > 0) { sum += anchor_loss(lp, lt, base + 2); cnt++; }
        if (t.w > 0) { sum += anchor_loss(lp, lt, base + 3); cnt++; }
    }

    // intra-block tree reduction
    #pragma unroll
    for (int off = 16; off > 0; off >>= 1) {
        sum += __shfl_xor_sync(0xFFFFFFFFu, sum, off);
        cnt += __shfl_xor_sync(0xFFFFFFFFu, cnt, off);
    }

    __shared__ float ssum[NWARPS];
    __shared__ int   scnt[NWARPS];
    __shared__ bool  s_last;
    int lane = threadIdx.x & 31;
    int wid  = threadIdx.x >> 5;
    if (lane == 0) { ssum[wid] = sum; scnt[wid] = cnt; }
    __syncthreads();

    if (wid == 0) {
        float s = (lane < NWARPS) ? ssum[lane] : 0.0f;
        int   c = (lane < NWARPS) ? scnt[lane] : 0;
        #pragma unroll
        for (int off = 16; off > 0; off >>= 1) {
            s += __shfl_xor_sync(0xFFFFFFFFu, s, off);
            c += __shfl_xor_sync(0xFFFFFFFFu, c, off);
        }
        if (lane == 0) {
            g_partial_sum[blockIdx.x] = s;
            g_partial_cnt[blockIdx.x] = c;
            __threadfence();
            int ticket = atomicAdd(&g_ticket, 1);
            s_last = (ticket == gridDim.x - 1);
        }
    }
    __syncthreads();

    // last-arriving block folds all partials (deterministic: fixed tree order)
    if (s_last) {
        float fs = 0.0f;
        int   fc = 0;
        for (int i = threadIdx.x; i < NBLOCKS; i += NTHREADS) {
            fs += ((volatile float*)g_partial_sum)[i];
            fc += ((volatile int*)g_partial_cnt)[i];
        }
        #pragma unroll
        for (int off = 16; off > 0; off >>= 1) {
            fs += __shfl_xor_sync(0xFFFFFFFFu, fs, off);
            fc += __shfl_xor_sync(0xFFFFFFFFu, fc, off);
        }
        if (lane == 0) { ssum[wid] = fs; scnt[wid] = fc; }
        __syncthreads();
        if (wid == 0) {
            float s2 = (lane < NWARPS) ? ssum[lane] : 0.0f;
            int   c2 = (lane < NWARPS) ? scnt[lane] : 0;
            #pragma unroll
            for (int off = 16; off > 0; off >>= 1) {
                s2 += __shfl_xor_sync(0xFFFFFFFFu, s2, off);
                c2 += __shfl_xor_sync(0xFFFFFFFFu, c2, off);
            }
            if (lane == 0) {
                out[0] = 0.2f * s2 / (float)c2;   // cls term exactly 0 for C=1
                g_ticket = 0;                     // reset for next graph replay
            }
        }
    }
}

extern "C" void kernel_launch(void* const* d_in, const int* in_sizes, int n_in,
                              void* d_out, int out_size)
{
    // inputs: loc_preds [B,A,8] f32, loc_targets [B,A,8] f32,
    //         cls_preds [B,A,1] f32 (UNUSED), cls_targets [B,A] i32
    const float4* lp = (const float4*)d_in[0];
    const float4* lt = (const float4*)d_in[1];
    const int4*   ct = (const int4*)d_in[3];
    float* out = (float*)d_out;

    int nAnchors = in_sizes[3];      // 3,200,000 (divisible by 4)
    int nGroups  = nAnchors >> 2;

    ohem_fused_kernel<<<NBLOCKS, NTHREADS>>>(lp, lt, ct, nGroups, out);
}

// round 3
// speedup vs baseline: 1.0436x; 1.0436x over previous
#include <cuda_runtime.h>
#include <cuda_bf16.h>

// OHEM loss, C=1 specialization:
//   ce == 0 exactly (logsumexp over singleton axis minus the gathered element),
//   so cls_loss == 0 and the hard-negative mining is dead code.
//   out = 0.2 * sum_{pos}(smoothL1(loc_preds - loc_targets)) / num_pos
//
// Evidence from R2: DRAM fill granularity ~128B makes mask-predicated loads
// worthless (full 217.6 MB moves regardless). So: branch-free unconditional
// streaming at max coalescing (anchor-per-thread), mask applied by multiply.
// Single kernel; last-arriving block folds partials (ticket + threadfence).

#define NBLOCKS  1184   // 148 SMs * 8 blocks -> one wave at occ 8
#define NTHREADS 256
#define NWARPS   (NTHREADS / 32)

__device__ float g_partial_sum[NBLOCKS];
__device__ int   g_partial_cnt[NBLOCKS];
__device__ int   g_ticket = 0;          // self-resets each run; deterministic

__device__ __forceinline__ float smooth_l1(float d) {
    float ax = fabsf(d);
    return (ax < 1.0f) ? 0.5f * d * d : ax - 0.5f;
}

__global__ __launch_bounds__(NTHREADS, 8)
void ohem_fused_kernel(const float4* __restrict__ lp,   // loc_preds  (2 float4/anchor)
                       const float4* __restrict__ lt,   // loc_targets
                       const int*    __restrict__ ct,   // cls_targets
                       int nAnchors,
                       float* __restrict__ out)
{
    float sum = 0.0f;
    int   cnt = 0;

    const int stride = gridDim.x * blockDim.x;
    for (int i = blockIdx.x * blockDim.x + threadIdx.x; i < nAnchors; i += stride) {
        int t = ct[i];
        // Unconditional, fully coalesced loads (branch-free streaming).
        float4 p0 = lp[2 * i];
        float4 p1 = lp[2 * i + 1];
        float4 t0 = lt[2 * i];
        float4 t1 = lt[2 * i + 1];

        float s = smooth_l1(p0.x - t0.x);
        s += smooth_l1(p0.y - t0.y);
        s += smooth_l1(p0.z - t0.z);
        s += smooth_l1(p0.w - t0.w);
        s += smooth_l1(p1.x - t1.x);
        s += smooth_l1(p1.y - t1.y);
        s += smooth_l1(p1.z - t1.z);
        s += smooth_l1(p1.w - t1.w);

        float m = (t > 0) ? 1.0f : 0.0f;   // SEL, no branch
        sum += m * s;
        cnt += (t > 0);
    }

    // intra-block tree reduction
    #pragma unroll
    for (int off = 16; off > 0; off >>= 1) {
        sum += __shfl_xor_sync(0xFFFFFFFFu, sum, off);
        cnt += __shfl_xor_sync(0xFFFFFFFFu, cnt, off);
    }

    __shared__ float ssum[NWARPS];
    __shared__ int   scnt[NWARPS];
    __shared__ bool  s_last;
    int lane = threadIdx.x & 31;
    int wid  = threadIdx.x >> 5;
    if (lane == 0) { ssum[wid] = sum; scnt[wid] = cnt; }
    __syncthreads();

    if (wid == 0) {
        float s = (lane < NWARPS) ? ssum[lane] : 0.0f;
        int   c = (lane < NWARPS) ? scnt[lane] : 0;
        #pragma unroll
        for (int off = 16; off > 0; off >>= 1) {
            s += __shfl_xor_sync(0xFFFFFFFFu, s, off);
            c += __shfl_xor_sync(0xFFFFFFFFu, c, off);
        }
        if (lane == 0) {
            g_partial_sum[blockIdx.x] = s;
            g_partial_cnt[blockIdx.x] = c;
            __threadfence();
            int ticket = atomicAdd(&g_ticket, 1);
            s_last = (ticket == gridDim.x - 1);
        }
    }
    __syncthreads();

    // last-arriving block folds all partials (fixed tree order: deterministic)
    if (s_last) {
        float fs = 0.0f;
        int   fc = 0;
        for (int i = threadIdx.x; i < NBLOCKS; i += NTHREADS) {
            fs += ((volatile float*)g_partial_sum)[i];
            fc += ((volatile int*)g_partial_cnt)[i];
        }
        #pragma unroll
        for (int off = 16; off > 0; off >>= 1) {
            fs += __shfl_xor_sync(0xFFFFFFFFu, fs, off);
            fc += __shfl_xor_sync(0xFFFFFFFFu, fc, off);
        }
        if (lane == 0) { ssum[wid] = fs; scnt[wid] = fc; }
        __syncthreads();
        if (wid == 0) {
            float s2 = (lane < NWARPS) ? ssum[lane] : 0.0f;
            int   c2 = (lane < NWARPS) ? scnt[lane] : 0;
            #pragma unroll
            for (int off = 16; off > 0; off >>= 1) {
                s2 += __shfl_xor_sync(0xFFFFFFFFu, s2, off);
                c2 += __shfl_xor_sync(0xFFFFFFFFu, c2, off);
            }
            if (lane == 0) {
                out[0] = 0.2f * s2 / (float)c2;   // cls term exactly 0 for C=1
                g_ticket = 0;                     // reset for next graph replay
            }
        }
    }
}

extern "C" void kernel_launch(void* const* d_in, const int* in_sizes, int n_in,
                              void* d_out, int out_size)
{
    // inputs: loc_preds [B,A,8] f32, loc_targets [B,A,8] f32,
    //         cls_preds [B,A,1] f32 (UNUSED), cls_targets [B,A] i32
    const float4* lp = (const float4*)d_in[0];
    const float4* lt = (const float4*)d_in[1];
    const int*    ct = (const int*)d_in[3];
    float* out = (float*)d_out;

    int nAnchors = in_sizes[3];      // 3,200,000

    ohem_fused_kernel<<<NBLOCKS, NTHREADS>>>(lp, lt, ct, nAnchors, out);
}

// round 4
// speedup vs baseline: 1.1070x; 1.0608x over previous
#include <cuda_runtime.h>
#include <cuda_bf16.h>

// OHEM loss, C=1 specialization:
//   ce == 0 exactly, so cls_loss == 0; hard-negative mining is dead code.
//   out = 0.2 * sum_{pos}(smoothL1(loc_preds - loc_targets)) / num_pos
//
// R1-style layout (anchor-per-thread, perfectly coalesced; 1 anchor = one 32B
// HBM sector) with PREDICATED loads: negative anchors skip their sectors.
// 2-way unroll with ct prefetched up front for deeper MLP.
// Single kernel; last-arriving block folds partials (ticket + threadfence).

#define NBLOCKS  1184   // 148 SMs * 8 blocks
#define NTHREADS 256
#define NWARPS   (NTHREADS / 32)

__device__ float g_partial_sum[NBLOCKS];
__device__ int   g_partial_cnt[NBLOCKS];
__device__ int   g_ticket = 0;          // self-resets each run; deterministic

__device__ __forceinline__ float smooth_l1(float d) {
    float ax = fabsf(d);
    return (ax < 1.0f) ? 0.5f * d * d : ax - 0.5f;
}

__device__ __forceinline__ float anchor_loss(const float4* __restrict__ lp,
                                             const float4* __restrict__ lt,
                                             int i) {
    float4 p0 = lp[2 * i];
    float4 p1 = lp[2 * i + 1];
    float4 t0 = lt[2 * i];
    float4 t1 = lt[2 * i + 1];
    float s = smooth_l1(p0.x - t0.x);
    s += smooth_l1(p0.y - t0.y);
    s += smooth_l1(p0.z - t0.z);
    s += smooth_l1(p0.w - t0.w);
    s += smooth_l1(p1.x - t1.x);
    s += smooth_l1(p1.y - t1.y);
    s += smooth_l1(p1.z - t1.z);
    s += smooth_l1(p1.w - t1.w);
    return s;
}

__global__ __launch_bounds__(NTHREADS, 8)
void ohem_fused_kernel(const float4* __restrict__ lp,   // loc_preds  (2 float4/anchor)
                       const float4* __restrict__ lt,   // loc_targets
                       const int*    __restrict__ ct,   // cls_targets
                       int nAnchors,
                       float* __restrict__ out)
{
    float sum = 0.0f;
    int   cnt = 0;

    const int stride  = gridDim.x * blockDim.x;
    const int stride2 = 2 * stride;
    int i = blockIdx.x * blockDim.x + threadIdx.x;

    // 2-way unrolled main loop: both ct loads issued before the bodies.
    for (; i + stride < nAnchors; i += stride2) {
        int ta = ct[i];
        int tb = ct[i + stride];
        if (ta > 0) { sum += anchor_loss(lp, lt, i);          cnt++; }
        if (tb > 0) { sum += anchor_loss(lp, lt, i + stride); cnt++; }
    }
    if (i < nAnchors) {
        int ta = ct[i];
        if (ta > 0) { sum += anchor_loss(lp, lt, i); cnt++; }
    }

    // intra-block tree reduction
    #pragma unroll
    for (int off = 16; off > 0; off >>= 1) {
        sum += __shfl_xor_sync(0xFFFFFFFFu, sum, off);
        cnt += __shfl_xor_sync(0xFFFFFFFFu, cnt, off);
    }

    __shared__ float ssum[NWARPS];
    __shared__ int   scnt[NWARPS];
    __shared__ bool  s_last;
    int lane = threadIdx.x & 31;
    int wid  = threadIdx.x >> 5;
    if (lane == 0) { ssum[wid] = sum; scnt[wid] = cnt; }
    __syncthreads();

    if (wid == 0) {
        float s = (lane < NWARPS) ? ssum[lane] : 0.0f;
        int   c = (lane < NWARPS) ? scnt[lane] : 0;
        #pragma unroll
        for (int off = 16; off > 0; off >>= 1) {
            s += __shfl_xor_sync(0xFFFFFFFFu, s, off);
            c += __shfl_xor_sync(0xFFFFFFFFu, c, off);
        }
        if (lane == 0) {
            g_partial_sum[blockIdx.x] = s;
            g_partial_cnt[blockIdx.x] = c;
            __threadfence();
            int ticket = atomicAdd(&g_ticket, 1);
            s_last = (ticket == gridDim.x - 1);
        }
    }
    __syncthreads();

    // last-arriving block folds all partials (fixed tree order: deterministic)
    if (s_last) {
        float fs = 0.0f;
        int   fc = 0;
        for (int k = threadIdx.x; k < NBLOCKS; k += NTHREADS) {
            fs += ((volatile float*)g_partial_sum)[k];
            fc += ((volatile int*)g_partial_cnt)[k];
        }
        #pragma unroll
        for (int off = 16; off > 0; off >>= 1) {
            fs += __shfl_xor_sync(0xFFFFFFFFu, fs, off);
            fc += __shfl_xor_sync(0xFFFFFFFFu, fc, off);
        }
        if (lane == 0) { ssum[wid] = fs; scnt[wid] = fc; }
        __syncthreads();
        if (wid == 0) {
            float s2 = (lane < NWARPS) ? ssum[lane] : 0.0f;
            int   c2 = (lane < NWARPS) ? scnt[lane] : 0;
            #pragma unroll
            for (int off = 16; off > 0; off >>= 1) {
                s2 += __shfl_xor_sync(0xFFFFFFFFu, s2, off);
                c2 += __shfl_xor_sync(0xFFFFFFFFu, c2, off);
            }
            if (lane == 0) {
                out[0] = 0.2f * s2 / (float)c2;   // cls term exactly 0 for C=1
                g_ticket = 0;                     // reset for next graph replay
            }
        }
    }
}

extern "C" void kernel_launch(void* const* d_in, const int* in_sizes, int n_in,
                              void* d_out, int out_size)
{
    // inputs: loc_preds [B,A,8] f32, loc_targets [B,A,8] f32,
    //         cls_preds [B,A,1] f32 (UNUSED), cls_targets [B,A] i32
    const float4* lp = (const float4*)d_in[0];
    const float4* lt = (const float4*)d_in[1];
    const int*    ct = (const int*)d_in[3];
    float* out = (float*)d_out;

    int nAnchors = in_sizes[3];      // 3,200,000

    ohem_fused_kernel<<<NBLOCKS, NTHREADS>>>(lp, lt, ct, nAnchors, out);
}